// round 7
// baseline (speedup 1.0000x reference)
#include <cuda_runtime.h>
#include <cstdint>

#define LSZ 6400
#define WDIM 80
#define NEGV -1e9f

// Output layout (float32), total 448000:
//   [0..12800) mkpts0, [12800..25600) mkpts1, [25600..32000) mask_v,
//   [32000..38400) score, [38400..448000) sa_ir_up [640][640]

__device__ unsigned long long g_rowpack[LSZ];
__device__ unsigned int       g_colmax[LSZ];
// Fragment-ordered operands (tf32 bit patterns), scale 1/sqrt(6.4) folded in.
// g_pA: [mtile 400][kstep 16 (0-7 hi, 8-15 lo)][lane 32][4]  = 819200 f
// g_pB: [ntile 800][kstep 16 (0-7 hi, 8-15 lo)][lane 32][2]  = 819200 f
__device__ __align__(16) float g_pA[819200];
__device__ __align__(16) float g_pB[819200];

__device__ __forceinline__ unsigned fenc(float f) {
    unsigned u = __float_as_uint(f);
    return (u & 0x80000000u) ? ~u : (u | 0x80000000u);
}
__device__ __forceinline__ float fdec(unsigned e) {
    return __uint_as_float((e & 0x80000000u) ? (e ^ 0x80000000u) : ~e);
}
__device__ __forceinline__ float tf32r(float x) {
    unsigned u;
    asm("cvt.rna.tf32.f32 %0, %1;" : "=r"(u) : "f"(x));
    return __uint_as_float(u);
}
__device__ __forceinline__ uint32_t smem_u32(const void* p) {
    uint32_t a;
    asm("{ .reg .u64 t; cvta.to.shared.u64 t, %1; cvt.u32.u64 %0, t; }" : "=r"(a) : "l"(p));
    return a;
}
__device__ __forceinline__ void cpa16(uint32_t dst, const void* src) {
    asm volatile("cp.async.cg.shared.global [%0], [%1], 16;" :: "r"(dst), "l"(src) : "memory");
}
__device__ __forceinline__ void mma_tf32(float* c, uint4 a, uint2 b) {
    asm volatile(
        "mma.sync.aligned.m16n8k8.row.col.f32.tf32.tf32.f32 "
        "{%0,%1,%2,%3}, {%4,%5,%6,%7}, {%8,%9}, {%0,%1,%2,%3};"
        : "+f"(c[0]), "+f"(c[1]), "+f"(c[2]), "+f"(c[3])
        : "r"(a.x), "r"(a.y), "r"(a.z), "r"(a.w), "r"(b.x), "r"(b.y));
}

__global__ void init_kernel() {
    int i = blockIdx.x * blockDim.x + threadIdx.x;
    if (i < LSZ) { g_rowpack[i] = 0ull; g_colmax[i] = 0u; }
}

// Split fp32 -> tf32 hi/lo with scale folded; emit directly in mma fragment order.
__global__ __launch_bounds__(256) void prep_kernel(const float* __restrict__ fA,
                                                   const float* __restrict__ fB) {
    const float s = 0.3952847075210474f;   // 1/sqrt(6.4)
    int b = blockIdx.x, tid = threadIdx.x;
    if (b < 800) {                          // ---- A fragments ----
        int idx = b * 256 + tid;            // 0..204799
        int lane = idx & 31, ks = (idx >> 5) & 15, mt = idx >> 9;
        int gid = lane >> 2, tig = lane & 3;
        int kb = (ks & 7) * 8; bool hip = ks < 8;
        int l0 = mt * 16 + gid, l1 = l0 + 8;
        uint4 o;
        {
            float v, h;
            v = fA[(kb + tig) * LSZ + l0] * s; h = tf32r(v);
            o.x = __float_as_uint(hip ? h : tf32r(v - h));
            v = fA[(kb + tig) * LSZ + l1] * s; h = tf32r(v);
            o.y = __float_as_uint(hip ? h : tf32r(v - h));
            v = fA[(kb + tig + 4) * LSZ + l0] * s; h = tf32r(v);
            o.z = __float_as_uint(hip ? h : tf32r(v - h));
            v = fA[(kb + tig + 4) * LSZ + l1] * s; h = tf32r(v);
            o.w = __float_as_uint(hip ? h : tf32r(v - h));
        }
        ((uint4*)g_pA)[idx] = o;
    } else {                                // ---- B fragments ----
        int idx = (b - 800) * 256 + tid;    // 0..409599
        int lane = idx & 31, ks = (idx >> 5) & 15, nt = idx >> 9;
        int gid = lane >> 2, tig = lane & 3;
        int kb = (ks & 7) * 8; bool hip = ks < 8;
        int n0 = nt * 8 + gid;
        uint2 o;
        {
            float v, h;
            v = fB[(kb + tig) * LSZ + n0] * s; h = tf32r(v);
            o.x = __float_as_uint(hip ? h : tf32r(v - h));
            v = fB[(kb + tig + 4) * LSZ + n0] * s; h = tf32r(v);
            o.y = __float_as_uint(hip ? h : tf32r(v - h));
        }
        ((uint2*)g_pB)[idx] = o;
    }
}

// -------- smem layout (bytes) --------
#define SM_A     0        // 8 mtiles * 16 ks * 512B = 65536
#define SM_B     65536    // 16 ntiles * 16 ks * 256B = 65536
#define SM_SCOL  131072   // 128 u32
#define SM_SVR   131584   // 128 u8
#define SM_SVJ   131712   // 128 u8
#define SM_TOTAL 131840

__global__ __launch_bounds__(256, 1)
void gemm_kernel(const float* __restrict__ saV, const float* __restrict__ saI) {
    extern __shared__ char smem[];
    const uint32_t sb = smem_u32(smem);
    const int tid = threadIdx.x;
    const int w = tid >> 5, lane = tid & 31;
    const int wm = w >> 1, wn = w & 1;
    const int gid = lane >> 2, tig = lane & 3;
    const int i0 = blockIdx.y * 128, j0 = blockIdx.x * 128;

    const char* gA = (const char*)(g_pA + blockIdx.y * 16384);
    const char* gB = (const char*)(g_pB + blockIdx.x * 16384);

    // phase-1 async copy: hi halves (A ks0-7 per mtile, B ks0-7 per ntile)
    for (int c = tid; c < 2048; c += 256) {
        int mt = c >> 8, o = (c & 255) * 16;
        cpa16(sb + SM_A + mt * 8192 + o, gA + mt * 8192 + o);
    }
    for (int c = tid; c < 2048; c += 256) {
        int nt = c >> 7, o = (c & 127) * 16;
        cpa16(sb + SM_B + nt * 4096 + o, gB + nt * 4096 + o);
    }
    asm volatile("cp.async.commit_group;" ::: "memory");
    // phase-2 async copy: lo halves
    for (int c = tid; c < 2048; c += 256) {
        int mt = c >> 8, o = (c & 255) * 16;
        cpa16(sb + SM_A + mt * 8192 + 4096 + o, gA + mt * 8192 + 4096 + o);
    }
    for (int c = tid; c < 2048; c += 256) {
        int nt = c >> 7, o = (c & 127) * 16;
        cpa16(sb + SM_B + nt * 4096 + 2048 + o, gB + nt * 4096 + 2048 + o);
    }
    asm volatile("cp.async.commit_group;" ::: "memory");

    if (tid < 128) {
        ((unsigned*)(smem + SM_SCOL))[tid] = 0u;
        ((char*)(smem + SM_SVR))[tid] = (saV[i0 + tid] > 0.f) ? 1 : 0;
        ((char*)(smem + SM_SVJ))[tid] = (saI[j0 + tid] > 0.f) ? 1 : 0;
    }

    float acc[2][8][4];
    #pragma unroll
    for (int m = 0; m < 2; ++m)
        #pragma unroll
        for (int nt = 0; nt < 8; ++nt)
            #pragma unroll
            for (int c = 0; c < 4; ++c) acc[m][nt][c] = 0.f;

    const char* smA = smem + SM_A;
    const char* smB = smem + SM_B;
    auto do8 = [&](int abase, int bbase) {
        #pragma unroll
        for (int s = 0; s < 8; ++s) {
            uint4 Af[2];
            #pragma unroll
            for (int m = 0; m < 2; ++m)
                Af[m] = *(const uint4*)(smA + (((2 * wm + m) * 16 + abase + s) * 512) + lane * 16);
            #pragma unroll
            for (int nt = 0; nt < 8; ++nt) {
                uint2 Bf = *(const uint2*)(smB + (((wn * 8 + nt) * 16 + bbase + s) * 256) + lane * 8);
                mma_tf32(acc[0][nt], Af[0], Bf);
                mma_tf32(acc[1][nt], Af[1], Bf);
            }
        }
    };

    asm volatile("cp.async.wait_group 1;" ::: "memory");
    __syncthreads();
    do8(0, 0);                       // hi * hi  (overlaps with lo copy)
    asm volatile("cp.async.wait_group 0;" ::: "memory");
    __syncthreads();
    do8(8, 0);                       // lo * hi
    do8(0, 8);                       // hi * lo

    // ---- epilogue: mask, row argmax, col max ----
    const char* svr = (const char*)(smem + SM_SVR);
    const char* svj = (const char*)(smem + SM_SVJ);
    unsigned* scol = (unsigned*)(smem + SM_SCOL);

    bool vcol[16];
    #pragma unroll
    for (int nt = 0; nt < 8; ++nt) {
        vcol[nt * 2]     = svj[wn * 64 + nt * 8 + tig * 2];
        vcol[nt * 2 + 1] = svj[wn * 64 + nt * 8 + tig * 2 + 1];
    }
    float colm[16];
    #pragma unroll
    for (int e = 0; e < 16; ++e) colm[e] = NEGV;

    #pragma unroll
    for (int m = 0; m < 2; ++m) {
        #pragma unroll
        for (int r = 0; r < 2; ++r) {
            const bool vr = svr[wm * 32 + m * 16 + r * 8 + gid];
            float rb = NEGV; int bj = 0;
            #pragma unroll
            for (int nt = 0; nt < 8; ++nt) {
                #pragma unroll
                for (int c = 0; c < 2; ++c) {
                    float v = acc[m][nt][r * 2 + c];
                    v = (vr && vcol[nt * 2 + c]) ? v : NEGV;
                    int jl = wn * 64 + nt * 8 + tig * 2 + c;
                    if (v > rb) { rb = v; bj = jl; }
                    colm[nt * 2 + c] = fmaxf(colm[nt * 2 + c], v);
                }
            }
            unsigned long long pk = ((unsigned long long)fenc(rb) << 32) | (unsigned)(j0 + bj);
            #pragma unroll
            for (int off = 1; off <= 2; off <<= 1) {
                unsigned long long o = __shfl_xor_sync(0xFFFFFFFFu, pk, off);
                if (o > pk) pk = o;
            }
            if (tig == 0)
                atomicMax(&g_rowpack[i0 + wm * 32 + m * 16 + r * 8 + gid], pk);
        }
    }
    #pragma unroll
    for (int e = 0; e < 16; ++e) {
        float cm = colm[e];
        #pragma unroll
        for (int off = 4; off <= 16; off <<= 1)
            cm = fmaxf(cm, __shfl_xor_sync(0xFFFFFFFFu, cm, off));
        if (gid == 0)
            atomicMax(&scol[wn * 64 + (e >> 1) * 8 + tig * 2 + (e & 1)], fenc(cm));
    }
    __syncthreads();
    if (tid < 128) atomicMax(&g_colmax[j0 + tid], scol[tid]);
}

__global__ void finalize_kernel(float* __restrict__ out) {
    int i = blockIdx.x * blockDim.x + threadIdx.x;
    if (i >= LSZ) return;
    out[2 * i]     = (float)((i % WDIM) * 8);
    out[2 * i + 1] = (float)((i / WDIM) * 8);
    unsigned long long p = g_rowpack[i];
    unsigned enc = (unsigned)(p >> 32);
    int aj = (int)(p & 0xFFFFFFFFull);
    float rm = fdec(enc);
    bool mv = (rm > 0.f) && (enc == g_colmax[aj]);
    int j = mv ? aj : 0;
    out[12800 + 2 * i]     = (float)((j % WDIM) * 8);
    out[12800 + 2 * i + 1] = (float)((j / WDIM) * 8);
    out[25600 + i] = mv ? 1.f : 0.f;
    out[32000 + i] = mv ? rm : 0.f;
}

__global__ void upsample_kernel(const float* __restrict__ sa, float* __restrict__ out) {
    int idx = blockIdx.x * blockDim.x + threadIdx.x;
    if (idx >= 640 * 640) return;
    int ox = idx % 640, oy = idx / 640;
    float fy = (float)(oy * 79) / 639.0f;
    float fx = (float)(ox * 79) / 639.0f;
    int y0 = (int)floorf(fy); int y1 = min(y0 + 1, 79); float wy = fy - (float)y0;
    int x0 = (int)floorf(fx); int x1 = min(x0 + 1, 79); float wx = fx - (float)x0;
    float v00 = sa[y0 * WDIM + x0], v01 = sa[y0 * WDIM + x1];
    float v10 = sa[y1 * WDIM + x0], v11 = sa[y1 * WDIM + x1];
    float r0 = v00 * (1.f - wy) + v10 * wy;
    float r1 = v01 * (1.f - wy) + v11 * wy;
    out[38400 + idx] = r0 * (1.f - wx) + r1 * wx;
}

extern "C" void kernel_launch(void* const* d_in, const int* in_sizes, int n_in,
                              void* d_out, int out_size) {
    const float* feat_reg_vi = (const float*)d_in[0];
    const float* feat_reg_ir = (const float*)d_in[1];
    const float* feat_sa_vi  = (const float*)d_in[2];
    const float* feat_sa_ir  = (const float*)d_in[3];
    float* out = (float*)d_out;

    cudaFuncSetAttribute(gemm_kernel, cudaFuncAttributeMaxDynamicSharedMemorySize, SM_TOTAL);

    init_kernel<<<(LSZ + 255) / 256, 256>>>();
    prep_kernel<<<2400, 256>>>(feat_reg_vi, feat_reg_ir);
    gemm_kernel<<<dim3(50, 50), 256, SM_TOTAL>>>(feat_sa_vi, feat_sa_ir);
    finalize_kernel<<<(LSZ + 255) / 256, 256>>>(out);
    upsample_kernel<<<(640 * 640 + 255) / 256, 256>>>(feat_sa_ir, out);
}

// round 8
// speedup vs baseline: 1.9553x; 1.9553x over previous
#include <cuda_runtime.h>
#include <cuda_fp16.h>
#include <cstdint>

#define LSZ 6400
#define WDIM 80
#define NEGV -1e9f

// Output layout (float32), total 448000:
//   [0..12800) mkpts0, [12800..25600) mkpts1, [25600..32000) mask_v,
//   [32000..38400) score, [38400..448000) sa_ir_up [640][640]

__device__ unsigned long long g_rowpack[LSZ];
__device__ unsigned int       g_colmax[LSZ];
// fp16 fragment-ordered operands, scale 1/sqrt(6.4) folded in, hi/lo split.
// g_pA4: [mt 400][ks 4][p 2][lane 32] uint4  (m16n8k16 A frags)
// g_pB2: [nt 800][ks 4][p 2][lane 32] uint2  (B frags)
__device__ __align__(16) uint4 g_pA4[102400];
__device__ __align__(16) uint2 g_pB2[204800];

__device__ __forceinline__ unsigned fenc(float f) {
    unsigned u = __float_as_uint(f);
    return (u & 0x80000000u) ? ~u : (u | 0x80000000u);
}
__device__ __forceinline__ float fdec(unsigned e) {
    return __uint_as_float((e & 0x80000000u) ? (e ^ 0x80000000u) : ~e);
}
__device__ __forceinline__ uint32_t smem_u32(const void* p) {
    uint32_t a;
    asm("{ .reg .u64 t; cvta.to.shared.u64 t, %1; cvt.u32.u64 %0, t; }" : "=r"(a) : "l"(p));
    return a;
}
__device__ __forceinline__ void cpa16(uint32_t dst, const void* src) {
    asm volatile("cp.async.cg.shared.global [%0], [%1], 16;" :: "r"(dst), "l"(src) : "memory");
}
__device__ __forceinline__ void mma_fp16(float* c, uint4 a, uint2 b) {
    asm volatile(
        "mma.sync.aligned.m16n8k16.row.col.f32.f16.f16.f32 "
        "{%0,%1,%2,%3}, {%4,%5,%6,%7}, {%8,%9}, {%0,%1,%2,%3};"
        : "+f"(c[0]), "+f"(c[1]), "+f"(c[2]), "+f"(c[3])
        : "r"(a.x), "r"(a.y), "r"(a.z), "r"(a.w), "r"(b.x), "r"(b.y));
}
// pack two floats into hi-half2 and lo-half2 (residual) bit patterns
__device__ __forceinline__ void split2(float v0, float v1, unsigned& h, unsigned& l) {
    __half h0 = __float2half_rn(v0), h1 = __float2half_rn(v1);
    __half l0 = __float2half_rn(v0 - __half2float(h0));
    __half l1 = __float2half_rn(v1 - __half2float(h1));
    h = (unsigned)__half_as_ushort(h0) | ((unsigned)__half_as_ushort(h1) << 16);
    l = (unsigned)__half_as_ushort(l0) | ((unsigned)__half_as_ushort(l1) << 16);
}

// blocks 0..199: A frags, 200..599: B frags, 600..624: zero-init reductions
__global__ __launch_bounds__(256) void prep_kernel(const float* __restrict__ fA,
                                                   const float* __restrict__ fB) {
    const float s = 0.3952847075210474f;   // 1/sqrt(6.4)
    int b = blockIdx.x, tid = threadIdx.x;
    if (b < 200) {
        int idx = b * 256 + tid;           // [mt][ks][lane] = 400*4*32
        int lane = idx & 31, ks = (idx >> 5) & 3, mt = idx >> 7;
        int gid = lane >> 2, tig = lane & 3;
        int l0 = mt * 16 + gid, l1 = l0 + 8;
        int k0 = ks * 16 + 2 * tig;
        uint4 H, L;
        split2(fA[k0 * LSZ + l0] * s,       fA[(k0 + 1) * LSZ + l0] * s, H.x, L.x);
        split2(fA[k0 * LSZ + l1] * s,       fA[(k0 + 1) * LSZ + l1] * s, H.y, L.y);
        split2(fA[(k0 + 8) * LSZ + l0] * s, fA[(k0 + 9) * LSZ + l0] * s, H.z, L.z);
        split2(fA[(k0 + 8) * LSZ + l1] * s, fA[(k0 + 9) * LSZ + l1] * s, H.w, L.w);
        int base = ((mt * 4 + ks) * 2) * 32 + lane;
        g_pA4[base] = H;
        g_pA4[base + 32] = L;
    } else if (b < 600) {
        int idx = (b - 200) * 256 + tid;   // [nt][ks][lane] = 800*4*32
        int lane = idx & 31, ks = (idx >> 5) & 3, nt = idx >> 7;
        int gid = lane >> 2, tig = lane & 3;
        int n0 = nt * 8 + gid;
        int k0 = ks * 16 + 2 * tig;
        uint2 H, L;
        split2(fB[k0 * LSZ + n0] * s,       fB[(k0 + 1) * LSZ + n0] * s, H.x, L.x);
        split2(fB[(k0 + 8) * LSZ + n0] * s, fB[(k0 + 9) * LSZ + n0] * s, H.y, L.y);
        int base = ((nt * 4 + ks) * 2) * 32 + lane;
        g_pB2[base] = H;
        g_pB2[base + 32] = L;
    } else {
        int i = (b - 600) * 256 + tid;
        if (i < LSZ) { g_rowpack[i] = 0ull; g_colmax[i] = 0u; }
    }
}

// -------- smem layout (bytes) --------
#define SM_A     0        // 8 mt * 4 ks * 2 p * 512B = 32768
#define SM_B     32768    // 16 nt * 4 ks * 2 p * 256B = 32768
#define SM_SCOL  65536    // 128 u32
#define SM_SVR   66048    // 128 u8
#define SM_SVJ   66176    // 128 u8
#define SM_TOTAL 66304

__global__ __launch_bounds__(256, 2)
void gemm_kernel(const float* __restrict__ saV, const float* __restrict__ saI) {
    extern __shared__ char smem[];
    const uint32_t sb = smem_u32(smem);
    const int tid = threadIdx.x;
    const int w = tid >> 5, lane = tid & 31;
    const int wm = w >> 1, wn = w & 1;
    const int gid = lane >> 2, tig = lane & 3;
    const int i0 = blockIdx.y * 128, j0 = blockIdx.x * 128;

    const char* gA = (const char*)g_pA4 + blockIdx.y * 32768;   // 8 mt * 4KB
    const char* gB = (const char*)g_pB2 + blockIdx.x * 32768;   // 16 nt * 2KB

    // group 0: hi halves (p=0)
    for (int c = tid; c < 1024; c += 256) {
        int mt = c >> 7, r = c & 127;                    // r = ks*32+lane
        int off = (mt * 256 + (r >> 5) * 64 + (r & 31)) * 16;
        cpa16(sb + SM_A + off, gA + off);
    }
    for (int c = tid; c < 1024; c += 256) {
        int nt = c >> 6, r = c & 63;                     // r = ks*16+lanepair
        int off = (nt * 256 + (r >> 4) * 64 + (r & 15) * 2) * 8;
        cpa16(sb + SM_B + off, gB + off);
    }
    asm volatile("cp.async.commit_group;" ::: "memory");
    // group 1: lo halves (p=1)
    for (int c = tid; c < 1024; c += 256) {
        int mt = c >> 7, r = c & 127;
        int off = (mt * 256 + (r >> 5) * 64 + 32 + (r & 31)) * 16;
        cpa16(sb + SM_A + off, gA + off);
    }
    for (int c = tid; c < 1024; c += 256) {
        int nt = c >> 6, r = c & 63;
        int off = (nt * 256 + (r >> 4) * 64 + 32 + (r & 15) * 2) * 8;
        cpa16(sb + SM_B + off, gB + off);
    }
    asm volatile("cp.async.commit_group;" ::: "memory");

    if (tid < 128) {
        ((unsigned*)(smem + SM_SCOL))[tid] = 0u;
        ((char*)(smem + SM_SVR))[tid] = (saV[i0 + tid] > 0.f) ? 1 : 0;
        ((char*)(smem + SM_SVJ))[tid] = (saI[j0 + tid] > 0.f) ? 1 : 0;
    }

    float acc[2][8][4];
    #pragma unroll
    for (int m = 0; m < 2; ++m)
        #pragma unroll
        for (int nt = 0; nt < 8; ++nt)
            #pragma unroll
            for (int c = 0; c < 4; ++c) acc[m][nt][c] = 0.f;

    auto pass = [&](int pA, int pB) {
        #pragma unroll
        for (int ks = 0; ks < 4; ++ks) {
            uint4 Af[2];
            #pragma unroll
            for (int m = 0; m < 2; ++m)
                Af[m] = *(const uint4*)(smem + SM_A +
                        (((2 * wm + m) * 256) + ks * 64 + pA * 32 + lane) * 16);
            #pragma unroll
            for (int nt = 0; nt < 8; ++nt) {
                uint2 Bf = *(const uint2*)(smem + SM_B +
                        (((wn * 8 + nt) * 256) + ks * 64 + pB * 32 + lane) * 8);
                mma_fp16(acc[0][nt], Af[0], Bf);
                mma_fp16(acc[1][nt], Af[1], Bf);
            }
        }
    };

    asm volatile("cp.async.wait_group 1;" ::: "memory");
    __syncthreads();
    pass(0, 0);                      // hi*hi (lo copies still in flight)
    asm volatile("cp.async.wait_group 0;" ::: "memory");
    __syncthreads();
    pass(1, 0);                      // lo*hi
    pass(0, 1);                      // hi*lo

    // ---- epilogue: mask, row argmax, col max ----
    const char* svr = (const char*)(smem + SM_SVR);
    const char* svj = (const char*)(smem + SM_SVJ);
    unsigned* scol = (unsigned*)(smem + SM_SCOL);

    bool vcol[16];
    #pragma unroll
    for (int nt = 0; nt < 8; ++nt) {
        vcol[nt * 2]     = svj[wn * 64 + nt * 8 + tig * 2];
        vcol[nt * 2 + 1] = svj[wn * 64 + nt * 8 + tig * 2 + 1];
    }
    float colm[16];
    #pragma unroll
    for (int e = 0; e < 16; ++e) colm[e] = NEGV;

    #pragma unroll
    for (int m = 0; m < 2; ++m) {
        #pragma unroll
        for (int r = 0; r < 2; ++r) {
            const bool vr = svr[wm * 32 + m * 16 + r * 8 + gid];
            float rb = NEGV; int bj = 0;
            #pragma unroll
            for (int nt = 0; nt < 8; ++nt) {
                #pragma unroll
                for (int c = 0; c < 2; ++c) {
                    float v = acc[m][nt][r * 2 + c];
                    v = (vr && vcol[nt * 2 + c]) ? v : NEGV;
                    int jl = wn * 64 + nt * 8 + tig * 2 + c;
                    if (v > rb) { rb = v; bj = jl; }
                    colm[nt * 2 + c] = fmaxf(colm[nt * 2 + c], v);
                }
            }
            unsigned long long pk = ((unsigned long long)fenc(rb) << 32) | (unsigned)(j0 + bj);
            #pragma unroll
            for (int off = 1; off <= 2; off <<= 1) {
                unsigned long long o = __shfl_xor_sync(0xFFFFFFFFu, pk, off);
                if (o > pk) pk = o;
            }
            if (tig == 0)
                atomicMax(&g_rowpack[i0 + wm * 32 + m * 16 + r * 8 + gid], pk);
        }
    }
    #pragma unroll
    for (int e = 0; e < 16; ++e) {
        float cm = colm[e];
        #pragma unroll
        for (int off = 4; off <= 16; off <<= 1)
            cm = fmaxf(cm, __shfl_xor_sync(0xFFFFFFFFu, cm, off));
        if (gid == 0)
            atomicMax(&scol[wn * 64 + (e >> 1) * 8 + tig * 2 + (e & 1)], fenc(cm));
    }
    __syncthreads();
    if (tid < 128) atomicMax(&g_colmax[j0 + tid], scol[tid]);
}

// merged finalize + upsample
__global__ void tail_kernel(const float* __restrict__ sa, float* __restrict__ out) {
    int idx = blockIdx.x * blockDim.x + threadIdx.x;
    if (idx < LSZ) {
        int i = idx;
        out[2 * i]     = (float)((i % WDIM) * 8);
        out[2 * i + 1] = (float)((i / WDIM) * 8);
        unsigned long long p = g_rowpack[i];
        unsigned enc = (unsigned)(p >> 32);
        int aj = (int)(p & 0xFFFFFFFFull);
        float rm = fdec(enc);
        bool mv = (rm > 0.f) && (enc == g_colmax[aj]);
        int j = mv ? aj : 0;
        out[12800 + 2 * i]     = (float)((j % WDIM) * 8);
        out[12800 + 2 * i + 1] = (float)((j / WDIM) * 8);
        out[25600 + i] = mv ? 1.f : 0.f;
        out[32000 + i] = mv ? rm : 0.f;
    }
    if (idx < 640 * 640) {
        int ox = idx % 640, oy = idx / 640;
        float fy = (float)(oy * 79) / 639.0f;
        float fx = (float)(ox * 79) / 639.0f;
        int y0 = (int)floorf(fy); int y1 = min(y0 + 1, 79); float wy = fy - (float)y0;
        int x0 = (int)floorf(fx); int x1 = min(x0 + 1, 79); float wx = fx - (float)x0;
        float v00 = sa[y0 * WDIM + x0], v01 = sa[y0 * WDIM + x1];
        float v10 = sa[y1 * WDIM + x0], v11 = sa[y1 * WDIM + x1];
        float r0 = v00 * (1.f - wy) + v10 * wy;
        float r1 = v01 * (1.f - wy) + v11 * wy;
        out[38400 + idx] = r0 * (1.f - wx) + r1 * wx;
    }
}

extern "C" void kernel_launch(void* const* d_in, const int* in_sizes, int n_in,
                              void* d_out, int out_size) {
    const float* feat_reg_vi = (const float*)d_in[0];
    const float* feat_reg_ir = (const float*)d_in[1];
    const float* feat_sa_vi  = (const float*)d_in[2];
    const float* feat_sa_ir  = (const float*)d_in[3];
    float* out = (float*)d_out;

    cudaFuncSetAttribute(gemm_kernel, cudaFuncAttributeMaxDynamicSharedMemorySize, SM_TOTAL);

    prep_kernel<<<625, 256>>>(feat_reg_vi, feat_reg_ir);
    gemm_kernel<<<dim3(50, 50), 256, SM_TOTAL>>>(feat_sa_vi, feat_sa_ir);
    tail_kernel<<<1600, 256>>>(feat_sa_ir, out);
}

// round 9
// speedup vs baseline: 1.9909x; 1.0182x over previous
#include <cuda_runtime.h>
#include <cuda_fp16.h>
#include <cstdint>

#define LSZ 6400
#define WDIM 80
#define NEGV -1e9f

// Output layout (float32), total 448000:
//   [0..12800) mkpts0, [12800..25600) mkpts1, [25600..32000) mask_v,
//   [32000..38400) score, [38400..448000) sa_ir_up [640][640]

__device__ unsigned long long g_rowpack[LSZ];
__device__ unsigned int       g_colmax[LSZ];
// fp16 fragment-ordered operands, scale 1/sqrt(6.4) folded in, hi/lo split.
// g_pA4: [mt 400][ks 4][p 2][lane 32] uint4  (m16n8k16 A frags)
// g_pB2: [nt 800][ks 4][p 2][lane 32] uint2  (B frags)
__device__ __align__(16) uint4 g_pA4[102400];
__device__ __align__(16) uint2 g_pB2[204800];

__device__ __forceinline__ unsigned fenc(float f) {
    unsigned u = __float_as_uint(f);
    return (u & 0x80000000u) ? ~u : (u | 0x80000000u);
}
__device__ __forceinline__ float fdec(unsigned e) {
    return __uint_as_float((e & 0x80000000u) ? (e ^ 0x80000000u) : ~e);
}
__device__ __forceinline__ uint32_t smem_u32(const void* p) {
    uint32_t a;
    asm("{ .reg .u64 t; cvta.to.shared.u64 t, %1; cvt.u32.u64 %0, t; }" : "=r"(a) : "l"(p));
    return a;
}
__device__ __forceinline__ void cpa16(uint32_t dst, const void* src) {
    asm volatile("cp.async.cg.shared.global [%0], [%1], 16;" :: "r"(dst), "l"(src) : "memory");
}
__device__ __forceinline__ void mma_fp16(float* c, uint4 a, uint2 b) {
    asm volatile(
        "mma.sync.aligned.m16n8k16.row.col.f32.f16.f16.f32 "
        "{%0,%1,%2,%3}, {%4,%5,%6,%7}, {%8,%9}, {%0,%1,%2,%3};"
        : "+f"(c[0]), "+f"(c[1]), "+f"(c[2]), "+f"(c[3])
        : "r"(a.x), "r"(a.y), "r"(a.z), "r"(a.w), "r"(b.x), "r"(b.y));
}
__device__ __forceinline__ void split2(float v0, float v1, unsigned& h, unsigned& l) {
    __half h0 = __float2half_rn(v0), h1 = __float2half_rn(v1);
    __half l0 = __float2half_rn(v0 - __half2float(h0));
    __half l1 = __float2half_rn(v1 - __half2float(h1));
    h = (unsigned)__half_as_ushort(h0) | ((unsigned)__half_as_ushort(h1) << 16);
    l = (unsigned)__half_as_ushort(l0) | ((unsigned)__half_as_ushort(l1) << 16);
}

// blocks 0..199: A frags; 200..599: B frags; 600..624: zero-init; 625..2224: upsample
__global__ __launch_bounds__(256) void prep_kernel(const float* __restrict__ fA,
                                                   const float* __restrict__ fB,
                                                   const float* __restrict__ saIR,
                                                   float* __restrict__ out) {
    const float s = 0.3952847075210474f;   // 1/sqrt(6.4)
    int b = blockIdx.x, tid = threadIdx.x;
    if (b < 200) {
        int idx = b * 256 + tid;
        int lane = idx & 31, ks = (idx >> 5) & 3, mt = idx >> 7;
        int gid = lane >> 2, tig = lane & 3;
        int l0 = mt * 16 + gid, l1 = l0 + 8;
        int k0 = ks * 16 + 2 * tig;
        uint4 H, L;
        split2(fA[k0 * LSZ + l0] * s,       fA[(k0 + 1) * LSZ + l0] * s, H.x, L.x);
        split2(fA[k0 * LSZ + l1] * s,       fA[(k0 + 1) * LSZ + l1] * s, H.y, L.y);
        split2(fA[(k0 + 8) * LSZ + l0] * s, fA[(k0 + 9) * LSZ + l0] * s, H.z, L.z);
        split2(fA[(k0 + 8) * LSZ + l1] * s, fA[(k0 + 9) * LSZ + l1] * s, H.w, L.w);
        int base = ((mt * 4 + ks) * 2) * 32 + lane;
        g_pA4[base] = H;
        g_pA4[base + 32] = L;
    } else if (b < 600) {
        int idx = (b - 200) * 256 + tid;
        int lane = idx & 31, ks = (idx >> 5) & 3, nt = idx >> 7;
        int gid = lane >> 2, tig = lane & 3;
        int n0 = nt * 8 + gid;
        int k0 = ks * 16 + 2 * tig;
        uint2 H, L;
        split2(fB[k0 * LSZ + n0] * s,       fB[(k0 + 1) * LSZ + n0] * s, H.x, L.x);
        split2(fB[(k0 + 8) * LSZ + n0] * s, fB[(k0 + 9) * LSZ + n0] * s, H.y, L.y);
        int base = ((nt * 4 + ks) * 2) * 32 + lane;
        g_pB2[base] = H;
        g_pB2[base + 32] = L;
    } else if (b < 625) {
        int i = (b - 600) * 256 + tid;
        if (i < LSZ) { g_rowpack[i] = 0ull; g_colmax[i] = 0u; }
    } else {
        int idx = (b - 625) * 256 + tid;           // 0..409599
        int ox = idx % 640, oy = idx / 640;
        float fy = (float)(oy * 79) / 639.0f;
        float fx = (float)(ox * 79) / 639.0f;
        int y0 = (int)floorf(fy); int y1 = min(y0 + 1, 79); float wy = fy - (float)y0;
        int x0 = (int)floorf(fx); int x1 = min(x0 + 1, 79); float wx = fx - (float)x0;
        float v00 = saIR[y0 * WDIM + x0], v01 = saIR[y0 * WDIM + x1];
        float v10 = saIR[y1 * WDIM + x0], v11 = saIR[y1 * WDIM + x1];
        float r0 = v00 * (1.f - wy) + v10 * wy;
        float r1 = v01 * (1.f - wy) + v11 * wy;
        out[38400 + idx] = r0 * (1.f - wx) + r1 * wx;
    }
}

// -------- smem layout (bytes) --------
#define SM_A     0        // 8 mt * 4 ks * 2 p * 512B = 32768
#define SM_B     32768    // 16 nt * 4 ks * 2 p * 256B = 32768
#define SM_SCOL  65536    // 128 u32
#define SM_SVR   66048    // 128 u8
#define SM_SVJ   66176    // 128 u8
#define SM_TOTAL 66304

__global__ __launch_bounds__(256, 2)
void gemm_kernel(const float* __restrict__ saV, const float* __restrict__ saI) {
    extern __shared__ char smem[];
    const uint32_t sb = smem_u32(smem);
    const int tid = threadIdx.x;
    const int w = tid >> 5, lane = tid & 31;
    const int wm = w >> 1, wn = w & 1;
    const int gid = lane >> 2, tig = lane & 3;
    const int i0 = blockIdx.y * 128, j0 = blockIdx.x * 128;

    const char* gA = (const char*)g_pA4 + blockIdx.y * 32768;
    const char* gB = (const char*)g_pB2 + blockIdx.x * 32768;

    #pragma unroll 1
    for (int c = tid; c < 2048; c += 256) cpa16(sb + SM_A + c * 16, gA + c * 16);
    #pragma unroll 1
    for (int c = tid; c < 2048; c += 256) cpa16(sb + SM_B + c * 16, gB + c * 16);
    asm volatile("cp.async.commit_group;" ::: "memory");

    if (tid < 128) {
        ((unsigned*)(smem + SM_SCOL))[tid] = 0u;
        ((char*)(smem + SM_SVR))[tid] = (saV[i0 + tid] > 0.f) ? 1 : 0;
        ((char*)(smem + SM_SVJ))[tid] = (saI[j0 + tid] > 0.f) ? 1 : 0;
    }

    float acc[2][8][4];
    #pragma unroll
    for (int m = 0; m < 2; ++m)
        #pragma unroll
        for (int nt = 0; nt < 8; ++nt)
            #pragma unroll
            for (int c = 0; c < 4; ++c) acc[m][nt][c] = 0.f;

    asm volatile("cp.async.wait_group 0;" ::: "memory");
    __syncthreads();

    // fused k-loop: load fragments once, issue all 3 compensation terms
    #pragma unroll
    for (int ks = 0; ks < 4; ++ks) {
        uint4 Ah[2], Al[2];
        #pragma unroll
        for (int m = 0; m < 2; ++m) {
            const char* ab = smem + SM_A + (((2 * wm + m) * 256) + ks * 64 + lane) * 16;
            Ah[m] = *(const uint4*)ab;
            Al[m] = *(const uint4*)(ab + 512);        // p=1 is +32 units of 16B
        }
        #pragma unroll
        for (int nt = 0; nt < 8; ++nt) {
            const char* bb = smem + SM_B + (((wn * 8 + nt) * 256) + ks * 64 + lane) * 8;
            uint2 Bh = *(const uint2*)bb;
            uint2 Bl = *(const uint2*)(bb + 256);     // p=1 is +32 units of 8B
            mma_fp16(acc[0][nt], Ah[0], Bh);
            mma_fp16(acc[1][nt], Ah[1], Bh);
            mma_fp16(acc[0][nt], Al[0], Bh);
            mma_fp16(acc[1][nt], Al[1], Bh);
            mma_fp16(acc[0][nt], Ah[0], Bl);
            mma_fp16(acc[1][nt], Ah[1], Bl);
        }
    }

    // ---- epilogue: mask, row argmax, col max ----
    const char* svr = (const char*)(smem + SM_SVR);
    const char* svj = (const char*)(smem + SM_SVJ);
    unsigned* scol = (unsigned*)(smem + SM_SCOL);

    bool vcol[16];
    #pragma unroll
    for (int nt = 0; nt < 8; ++nt) {
        vcol[nt * 2]     = svj[wn * 64 + nt * 8 + tig * 2];
        vcol[nt * 2 + 1] = svj[wn * 64 + nt * 8 + tig * 2 + 1];
    }
    float colm[16];
    #pragma unroll
    for (int e = 0; e < 16; ++e) colm[e] = NEGV;

    #pragma unroll
    for (int m = 0; m < 2; ++m) {
        #pragma unroll
        for (int r = 0; r < 2; ++r) {
            const bool vr = svr[wm * 32 + m * 16 + r * 8 + gid];
            float rb = NEGV; int bj = 0;
            #pragma unroll
            for (int nt = 0; nt < 8; ++nt) {
                #pragma unroll
                for (int c = 0; c < 2; ++c) {
                    float v = acc[m][nt][r * 2 + c];
                    v = (vr && vcol[nt * 2 + c]) ? v : NEGV;
                    int jl = wn * 64 + nt * 8 + tig * 2 + c;
                    if (v > rb) { rb = v; bj = jl; }
                    colm[nt * 2 + c] = fmaxf(colm[nt * 2 + c], v);
                }
            }
            unsigned long long pk = ((unsigned long long)fenc(rb) << 32) | (unsigned)(j0 + bj);
            #pragma unroll
            for (int off = 1; off <= 2; off <<= 1) {
                unsigned long long o = __shfl_xor_sync(0xFFFFFFFFu, pk, off);
                if (o > pk) pk = o;
            }
            if (tig == 0)
                atomicMax(&g_rowpack[i0 + wm * 32 + m * 16 + r * 8 + gid], pk);
        }
    }
    #pragma unroll
    for (int e = 0; e < 16; ++e) {
        float cm = colm[e];
        #pragma unroll
        for (int off = 4; off <= 16; off <<= 1)
            cm = fmaxf(cm, __shfl_xor_sync(0xFFFFFFFFu, cm, off));
        if (gid == 0)
            atomicMax(&scol[wn * 64 + (e >> 1) * 8 + tig * 2 + (e & 1)], fenc(cm));
    }
    __syncthreads();
    if (tid < 128) atomicMax(&g_colmax[j0 + tid], scol[tid]);
}

__global__ void tail_kernel(float* __restrict__ out) {
    int i = blockIdx.x * blockDim.x + threadIdx.x;
    if (i >= LSZ) return;
    out[2 * i]     = (float)((i % WDIM) * 8);
    out[2 * i + 1] = (float)((i / WDIM) * 8);
    unsigned long long p = g_rowpack[i];
    unsigned enc = (unsigned)(p >> 32);
    int aj = (int)(p & 0xFFFFFFFFull);
    float rm = fdec(enc);
    bool mv = (rm > 0.f) && (enc == g_colmax[aj]);
    int j = mv ? aj : 0;
    out[12800 + 2 * i]     = (float)((j % WDIM) * 8);
    out[12800 + 2 * i + 1] = (float)((j / WDIM) * 8);
    out[25600 + i] = mv ? 1.f : 0.f;
    out[32000 + i] = mv ? rm : 0.f;
}

extern "C" void kernel_launch(void* const* d_in, const int* in_sizes, int n_in,
                              void* d_out, int out_size) {
    const float* feat_reg_vi = (const float*)d_in[0];
    const float* feat_reg_ir = (const float*)d_in[1];
    const float* feat_sa_vi  = (const float*)d_in[2];
    const float* feat_sa_ir  = (const float*)d_in[3];
    float* out = (float*)d_out;

    cudaFuncSetAttribute(gemm_kernel, cudaFuncAttributeMaxDynamicSharedMemorySize, SM_TOTAL);

    prep_kernel<<<2225, 256>>>(feat_reg_vi, feat_reg_ir, feat_sa_ir, out);
    gemm_kernel<<<dim3(50, 50), 256, SM_TOTAL>>>(feat_sa_vi, feat_sa_ir);
    tail_kernel<<<25, 256>>>(out);
}

// round 10
// speedup vs baseline: 3.3313x; 1.6733x over previous
#include <cuda_runtime.h>
#include <cuda_fp16.h>
#include <cstdint>

#define LSZ 6400
#define WDIM 80
#define NEGV -1e9f

// Output layout (float32), total 448000:
//   [0..12800) mkpts0, [12800..25600) mkpts1, [25600..32000) mask_v,
//   [32000..38400) score, [38400..448000) sa_ir_up [640][640]

__device__ unsigned long long g_rowpack[LSZ];
__device__ unsigned int       g_colmax[LSZ];
__device__ int g_cntR, g_cntC;
__device__ int g_rowidx[LSZ];
__device__ int g_colidx[LSZ];
// fp16 fragment-ordered compacted operands, scale 1/sqrt(6.4) folded, hi/lo split.
// g_pA4: [mt 400][ks 4][p 2][lane 32] uint4 ; g_pB2: [nt 800][ks 4][p 2][lane 32] uint2
__device__ __align__(16) uint4 g_pA4[102400];
__device__ __align__(16) uint2 g_pB2[204800];

__device__ __forceinline__ unsigned fenc(float f) {
    unsigned u = __float_as_uint(f);
    return (u & 0x80000000u) ? ~u : (u | 0x80000000u);
}
__device__ __forceinline__ float fdec(unsigned e) {
    return __uint_as_float((e & 0x80000000u) ? (e ^ 0x80000000u) : ~e);
}
__device__ __forceinline__ uint32_t smem_u32(const void* p) {
    uint32_t a;
    asm("{ .reg .u64 t; cvta.to.shared.u64 t, %1; cvt.u32.u64 %0, t; }" : "=r"(a) : "l"(p));
    return a;
}
__device__ __forceinline__ void cpa16(uint32_t dst, const void* src) {
    asm volatile("cp.async.cg.shared.global [%0], [%1], 16;" :: "r"(dst), "l"(src) : "memory");
}
__device__ __forceinline__ void mma_fp16(float* c, uint4 a, uint2 b) {
    asm volatile(
        "mma.sync.aligned.m16n8k16.row.col.f32.f16.f16.f32 "
        "{%0,%1,%2,%3}, {%4,%5,%6,%7}, {%8,%9}, {%0,%1,%2,%3};"
        : "+f"(c[0]), "+f"(c[1]), "+f"(c[2]), "+f"(c[3])
        : "r"(a.x), "r"(a.y), "r"(a.z), "r"(a.w), "r"(b.x), "r"(b.y));
}
__device__ __forceinline__ void split2(float v0, float v1, unsigned& h, unsigned& l) {
    __half h0 = __float2half_rn(v0), h1 = __float2half_rn(v1);
    __half l0 = __float2half_rn(v0 - __half2float(h0));
    __half l1 = __float2half_rn(v1 - __half2float(h1));
    h = (unsigned)__half_as_ushort(h0) | ((unsigned)__half_as_ushort(h1) << 16);
    l = (unsigned)__half_as_ushort(l0) | ((unsigned)__half_as_ushort(l1) << 16);
}

// block 0: compact rows; block 1: compact cols; blocks 2..26: zero-init reductions
__global__ __launch_bounds__(256) void compact_kernel(const float* __restrict__ saV,
                                                      const float* __restrict__ saI) {
    int b = blockIdx.x, tid = threadIdx.x;
    if (b < 2) {
        const float* sa = b ? saI : saV;
        int* idxout = b ? g_colidx : g_rowidx;
        __shared__ int wsum[8];
        __shared__ int soff;
        if (tid == 0) soff = 0;
        __syncthreads();
        int lane = tid & 31, w = tid >> 5;
        for (int c = 0; c < 25; ++c) {
            int i = c * 256 + tid;
            int v = sa[i] > 0.f;
            unsigned m = __ballot_sync(0xFFFFFFFFu, v);
            if (lane == 31) wsum[w] = __popc(m);
            int wpre = __popc(m & ((1u << lane) - 1u));
            __syncthreads();
            int base = soff, wbase = 0;
            for (int k = 0; k < w; ++k) wbase += wsum[k];
            if (v) idxout[base + wbase + wpre] = i;
            __syncthreads();
            if (tid == 0) {
                int t = 0;
                for (int k = 0; k < 8; ++k) t += wsum[k];
                soff += t;
            }
            __syncthreads();
        }
        if (tid == 0) { if (b) g_cntC = soff; else g_cntR = soff; }
    } else {
        int i = (b - 2) * 256 + tid;
        if (i < LSZ) { g_rowpack[i] = 0ull; g_colmax[i] = 0u; }
    }
}

// blocks 0..199: A frags (compacted rows); 200..599: B frags; 600..2199: upsample
__global__ __launch_bounds__(256) void prep_kernel(const float* __restrict__ fA,
                                                   const float* __restrict__ fB,
                                                   const float* __restrict__ saIR,
                                                   float* __restrict__ out) {
    const float s = 0.3952847075210474f;   // 1/sqrt(6.4)
    int b = blockIdx.x, tid = threadIdx.x;
    if (b < 200) {
        int cntR = g_cntR;
        int nmt = ((cntR + 127) >> 7) * 8;           // mtiles needed
        if (2 * b >= nmt) return;
        int idx = b * 256 + tid;
        int lane = idx & 31, ks = (idx >> 5) & 3, mt = idx >> 7;
        int gid = lane >> 2, tig = lane & 3;
        int s0 = mt * 16 + gid, s1 = s0 + 8;
        int l0 = (s0 < cntR) ? g_rowidx[s0] : 0;
        int l1 = (s1 < cntR) ? g_rowidx[s1] : 0;
        int k0 = ks * 16 + 2 * tig;
        uint4 H, L;
        split2(fA[k0 * LSZ + l0] * s,       fA[(k0 + 1) * LSZ + l0] * s, H.x, L.x);
        split2(fA[k0 * LSZ + l1] * s,       fA[(k0 + 1) * LSZ + l1] * s, H.y, L.y);
        split2(fA[(k0 + 8) * LSZ + l0] * s, fA[(k0 + 9) * LSZ + l0] * s, H.z, L.z);
        split2(fA[(k0 + 8) * LSZ + l1] * s, fA[(k0 + 9) * LSZ + l1] * s, H.w, L.w);
        int base = ((mt * 4 + ks) * 2) * 32 + lane;
        g_pA4[base] = H;
        g_pA4[base + 32] = L;
    } else if (b < 600) {
        int cntC = g_cntC;
        int nnt = ((cntC + 127) >> 7) * 16;          // ntiles needed
        if (2 * (b - 200) >= nnt) return;
        int idx = (b - 200) * 256 + tid;
        int lane = idx & 31, ks = (idx >> 5) & 3, nt = idx >> 7;
        int gid = lane >> 2, tig = lane & 3;
        int sl = nt * 8 + gid;
        int n0 = (sl < cntC) ? g_colidx[sl] : 0;
        int k0 = ks * 16 + 2 * tig;
        uint2 H, L;
        split2(fB[k0 * LSZ + n0] * s,       fB[(k0 + 1) * LSZ + n0] * s, H.x, L.x);
        split2(fB[(k0 + 8) * LSZ + n0] * s, fB[(k0 + 9) * LSZ + n0] * s, H.y, L.y);
        int base = ((nt * 4 + ks) * 2) * 32 + lane;
        g_pB2[base] = H;
        g_pB2[base + 32] = L;
    } else {
        int idx = (b - 600) * 256 + tid;             // 0..409599
        int ox = idx % 640, oy = idx / 640;
        float fy = (float)(oy * 79) / 639.0f;
        float fx = (float)(ox * 79) / 639.0f;
        int y0 = (int)floorf(fy); int y1 = min(y0 + 1, 79); float wy = fy - (float)y0;
        int x0 = (int)floorf(fx); int x1 = min(x0 + 1, 79); float wx = fx - (float)x0;
        float v00 = saIR[y0 * WDIM + x0], v01 = saIR[y0 * WDIM + x1];
        float v10 = saIR[y1 * WDIM + x0], v11 = saIR[y1 * WDIM + x1];
        float r0 = v00 * (1.f - wy) + v10 * wy;
        float r1 = v01 * (1.f - wy) + v11 * wy;
        out[38400 + idx] = r0 * (1.f - wx) + r1 * wx;
    }
}

// -------- smem layout (bytes) --------
#define SM_A     0        // 32768
#define SM_B     32768    // 32768
#define SM_SCOL  65536    // 128 u32
#define SM_SCID  66048    // 128 u32 (real col indices)
#define SM_TOTAL 66560

__global__ __launch_bounds__(256, 2)
void gemm_kernel() {
    const int cntR = g_cntR, cntC = g_cntC;
    const int nRt = (cntR + 127) >> 7, nCt = (cntC + 127) >> 7;
    if ((int)blockIdx.y >= nRt || (int)blockIdx.x >= nCt) return;

    extern __shared__ char smem[];
    const uint32_t sb = smem_u32(smem);
    const int tid = threadIdx.x;
    const int w = tid >> 5, lane = tid & 31;
    const int wm = w >> 1, wn = w & 1;
    const int gid = lane >> 2, tig = lane & 3;
    const int i0 = blockIdx.y * 128, j0 = blockIdx.x * 128;

    const char* gA = (const char*)g_pA4 + blockIdx.y * 32768;
    const char* gB = (const char*)g_pB2 + blockIdx.x * 32768;

    #pragma unroll 1
    for (int c = tid; c < 2048; c += 256) cpa16(sb + SM_A + c * 16, gA + c * 16);
    #pragma unroll 1
    for (int c = tid; c < 2048; c += 256) cpa16(sb + SM_B + c * 16, gB + c * 16);
    asm volatile("cp.async.commit_group;" ::: "memory");

    if (tid < 128) {
        ((unsigned*)(smem + SM_SCOL))[tid] = 0u;
        ((int*)(smem + SM_SCID))[tid] = (j0 + tid < cntC) ? g_colidx[j0 + tid] : 0;
    }

    float acc[2][8][4];
    #pragma unroll
    for (int m = 0; m < 2; ++m)
        #pragma unroll
        for (int nt = 0; nt < 8; ++nt)
            #pragma unroll
            for (int c = 0; c < 4; ++c) acc[m][nt][c] = 0.f;

    asm volatile("cp.async.wait_group 0;" ::: "memory");
    __syncthreads();

    #pragma unroll
    for (int ks = 0; ks < 4; ++ks) {
        uint4 Ah[2], Al[2];
        #pragma unroll
        for (int m = 0; m < 2; ++m) {
            const char* ab = smem + SM_A + (((2 * wm + m) * 256) + ks * 64 + lane) * 16;
            Ah[m] = *(const uint4*)ab;
            Al[m] = *(const uint4*)(ab + 512);
        }
        #pragma unroll
        for (int nt = 0; nt < 8; ++nt) {
            const char* bb = smem + SM_B + (((wn * 8 + nt) * 256) + ks * 64 + lane) * 8;
            uint2 Bh = *(const uint2*)bb;
            uint2 Bl = *(const uint2*)(bb + 256);
            mma_fp16(acc[0][nt], Ah[0], Bh);
            mma_fp16(acc[1][nt], Ah[1], Bh);
            mma_fp16(acc[0][nt], Al[0], Bh);
            mma_fp16(acc[1][nt], Al[1], Bh);
            mma_fp16(acc[0][nt], Ah[0], Bl);
            mma_fp16(acc[1][nt], Ah[1], Bl);
        }
    }

    // ---- epilogue: bounds-mask, row argmax (scatter), col max (scatter) ----
    unsigned* scol = (unsigned*)(smem + SM_SCOL);
    const int* scid = (const int*)(smem + SM_SCID);

    bool vcol[16];
    int rcol[16];
    #pragma unroll
    for (int nt = 0; nt < 8; ++nt) {
        #pragma unroll
        for (int c = 0; c < 2; ++c) {
            int jl = wn * 64 + nt * 8 + tig * 2 + c;
            vcol[nt * 2 + c] = (j0 + jl) < cntC;
            rcol[nt * 2 + c] = scid[jl];
        }
    }
    float colm[16];
    #pragma unroll
    for (int e = 0; e < 16; ++e) colm[e] = NEGV;

    #pragma unroll
    for (int m = 0; m < 2; ++m) {
        #pragma unroll
        for (int r = 0; r < 2; ++r) {
            const int slot = i0 + wm * 32 + m * 16 + r * 8 + gid;
            const bool vr = slot < cntR;
            float rb = NEGV; int bj = 0;
            #pragma unroll
            for (int nt = 0; nt < 8; ++nt) {
                #pragma unroll
                for (int c = 0; c < 2; ++c) {
                    float v = acc[m][nt][r * 2 + c];
                    v = (vr && vcol[nt * 2 + c]) ? v : NEGV;
                    if (v > rb) { rb = v; bj = rcol[nt * 2 + c]; }
                    colm[nt * 2 + c] = fmaxf(colm[nt * 2 + c], v);
                }
            }
            unsigned long long pk = ((unsigned long long)fenc(rb) << 32) | (unsigned)bj;
            #pragma unroll
            for (int off = 1; off <= 2; off <<= 1) {
                unsigned long long o = __shfl_xor_sync(0xFFFFFFFFu, pk, off);
                if (o > pk) pk = o;
            }
            if (tig == 0 && vr)
                atomicMax(&g_rowpack[g_rowidx[slot]], pk);
        }
    }
    #pragma unroll
    for (int e = 0; e < 16; ++e) {
        float cm = colm[e];
        #pragma unroll
        for (int off = 4; off <= 16; off <<= 1)
            cm = fmaxf(cm, __shfl_xor_sync(0xFFFFFFFFu, cm, off));
        if (gid == 0)
            atomicMax(&scol[wn * 64 + (e >> 1) * 8 + tig * 2 + (e & 1)], fenc(cm));
    }
    __syncthreads();
    if (tid < 128 && (j0 + tid) < cntC)
        atomicMax(&g_colmax[scid[tid]], scol[tid]);
}

__global__ void tail_kernel(float* __restrict__ out) {
    int i = blockIdx.x * blockDim.x + threadIdx.x;
    if (i >= LSZ) return;
    out[2 * i]     = (float)((i % WDIM) * 8);
    out[2 * i + 1] = (float)((i / WDIM) * 8);
    unsigned long long p = g_rowpack[i];
    unsigned enc = (unsigned)(p >> 32);
    int aj = (int)(p & 0xFFFFFFFFull);
    float rm = fdec(enc);
    bool mv = (rm > 0.f) && (enc == g_colmax[aj]);
    int j = mv ? aj : 0;
    out[12800 + 2 * i]     = (float)((j % WDIM) * 8);
    out[12800 + 2 * i + 1] = (float)((j / WDIM) * 8);
    out[25600 + i] = mv ? 1.f : 0.f;
    out[32000 + i] = mv ? rm : 0.f;
}

extern "C" void kernel_launch(void* const* d_in, const int* in_sizes, int n_in,
                              void* d_out, int out_size) {
    const float* feat_reg_vi = (const float*)d_in[0];
    const float* feat_reg_ir = (const float*)d_in[1];
    const float* feat_sa_vi  = (const float*)d_in[2];
    const float* feat_sa_ir  = (const float*)d_in[3];
    float* out = (float*)d_out;

    cudaFuncSetAttribute(gemm_kernel, cudaFuncAttributeMaxDynamicSharedMemorySize, SM_TOTAL);

    compact_kernel<<<27, 256>>>(feat_sa_vi, feat_sa_ir);
    prep_kernel<<<2200, 256>>>(feat_reg_vi, feat_reg_ir, feat_sa_ir, out);
    gemm_kernel<<<dim3(50, 50), 256, SM_TOTAL>>>();
    tail_kernel<<<25, 256>>>(out);
}